// round 8
// baseline (speedup 1.0000x reference)
#include <cuda_runtime.h>
#include <cuda_fp16.h>
#include <cstdint>

// TopKNoisyRouter: fused dual GEMM [N,1024]x[1024,128], fp16 2-way split
// (3 HMMA products, fp32 accum, W pre-scaled by 32). KC=32 pipeline with the
// x fp32->fp16 convert for chunk c+1 and the x LDG for chunk c+2 interleaved
// INSIDE chunk c's MMA phase. B via cp.async at distance 2.
// Sync protocol (race-free): end of each chunk does
//   commit G(c+2) -> cp.async.wait_group 1 -> __syncthreads
// so every thread's group G(c+1) is complete BEFORE the barrier publishes it
// to all threads (cp.async groups are per-thread; round 7 waited after the
// barrier, which let threads read peers' unfinished copies).
// 2 CTAs/SM. Fused noisy-top-2 + softmax epilogue.

#define DK 1024
#define NE 64
#define BM 128
#define KC 32
#define NCHUNK (DK / KC)      // 32
#define PLANE 8192            // 128 rows x 32 fp16 (64B rows)
#define OFF_B (4 * PLANE)     // A: 2 bufs x 2 planes; B: same, after A
#define SMEM_BYTES 100352     // max(gemm 64KB, epilogue C+eps staging)

__device__ __half g_w[2][128 * DK];   // fp16(32w), fp16(32w - hi); K-major

__device__ __forceinline__ uint32_t smem_u32(const void* p) {
    uint32_t a;
    asm("{ .reg .u64 t; cvta.to.shared.u64 t, %1; cvt.u32.u64 %0, t; }" : "=r"(a) : "l"(p));
    return a;
}
__device__ __forceinline__ uint32_t swz32(uint32_t r, uint32_t c) {
    return (r >> 1) * 128 + (r & 1) * 64 + (c ^ (((r >> 1) & 3) << 4));
}
__device__ __forceinline__ void cp16(uint32_t dst, const void* src) {
    asm volatile("cp.async.cg.shared.global [%0], [%1], 16;" :: "r"(dst), "l"(src));
}
__device__ __forceinline__ void ldsm4(uint32_t& r0, uint32_t& r1, uint32_t& r2,
                                      uint32_t& r3, uint32_t addr) {
    asm volatile("ldmatrix.sync.aligned.m8n8.x4.shared.b16 {%0,%1,%2,%3}, [%4];"
                 : "=r"(r0), "=r"(r1), "=r"(r2), "=r"(r3) : "r"(addr));
}
__device__ __forceinline__ void mma16816(float* c, const uint32_t* a,
                                         uint32_t b0, uint32_t b1) {
    asm volatile("mma.sync.aligned.m16n8k16.row.col.f32.f16.f16.f32 "
                 "{%0,%1,%2,%3}, {%4,%5,%6,%7}, {%8,%9}, {%0,%1,%2,%3};"
                 : "+f"(c[0]), "+f"(c[1]), "+f"(c[2]), "+f"(c[3])
                 : "r"(a[0]), "r"(a[1]), "r"(a[2]), "r"(a[3]), "r"(b0), "r"(b1));
}
__device__ __forceinline__ float softplusf(float v) {
    return fmaxf(v, 0.0f) + log1pf(expf(-fabsf(v)));
}
__device__ __forceinline__ uint32_t pack_h2(__half lo, __half hi) {
    return (uint32_t)__half_as_ushort(lo) | ((uint32_t)__half_as_ushort(hi) << 16);
}

__global__ void prep_weights(const float* __restrict__ wr, const float* __restrict__ wn) {
    int i = blockIdx.x * blockDim.x + threadIdx.x;    // 0 .. 128*1024-1
    int e = i >> 10, k = i & 1023;
    float v = 32.0f * ((e < NE) ? wr[e * DK + k] : wn[(e - NE) * DK + k]);
    __half h = __float2half_rn(v);
    g_w[0][i] = h;
    g_w[1][i] = __float2half_rn(v - __half2float(h));
}

__global__ __launch_bounds__(256, 2)
void router_gemm(const float* __restrict__ x, const float* __restrict__ eps,
                 float* __restrict__ out, float* __restrict__ idx_out, int write_idx)
{
    extern __shared__ char smem[];
    const uint32_t sb = smem_u32(smem);
    const int tid = threadIdx.x;
    const int lane = tid & 31, wid = tid >> 5;
    const int wm = wid & 1, wq = wid >> 1;        // warp tile 64x32 at (wm*64, wq*32)
    const int row0 = blockIdx.x * BM;

    // coalesced zero-fill of this block's output tile [128 x 64]
    {
        float4 z = make_float4(0.f, 0.f, 0.f, 0.f);
        float4* ot = (float4*)(out + (size_t)row0 * NE);
        #pragma unroll
        for (int i = 0; i < 8; ++i) ot[tid + 256 * i] = z;
    }

    // ldmatrix per-lane address pieces
    const int rA = wm * 64 + (lane & 15);
    const uint32_t rowA = (uint32_t)((rA >> 1) * 128 + (rA & 1) * 64);
    const uint32_t xorA = (uint32_t)(((rA >> 1) & 3) << 4);
    const uint32_t cbA  = (uint32_t)((lane >> 4) * 16);
    const int rB = wq * 32 + (lane & 7) + ((lane >> 4) << 3);
    const uint32_t rowB = (uint32_t)((rB >> 1) * 128 + (rB & 1) * 64);
    const uint32_t xorB = (uint32_t)(((rB >> 1) & 3) << 4);
    const uint32_t cbB  = (uint32_t)(((lane >> 3) & 1) * 16);

    // x staging: thread covers row r_x, 16 floats at float-offset h_x
    const int r_x = tid >> 1;
    const int h_x = (tid & 1) * 16;
    const float* xbase = x + (size_t)(row0 + r_x) * DK + h_x;
    const uint32_t rowX = (uint32_t)((r_x >> 1) * 128 + (r_x & 1) * 64);
    const uint32_t xorX = (uint32_t)(((r_x >> 1) & 3) << 4);

    float acc[4][4][4];
    #pragma unroll
    for (int mt = 0; mt < 4; ++mt)
        #pragma unroll
        for (int nt = 0; nt < 4; ++nt)
            #pragma unroll
            for (int q = 0; q < 4; ++q) acc[mt][nt][q] = 0.f;

    // ---- prologue ----
    float4 xr[4];
    // x chunk0 -> regs -> convert into A[0]
    #pragma unroll
    for (int i = 0; i < 4; ++i) xr[i] = *(const float4*)(xbase + 4 * i);
    #pragma unroll
    for (int i = 0; i < 4; ++i) {
        const uint32_t sw = rowX + (((uint32_t)((h_x + 4 * i) * 2)) ^ xorX);
        float f[4] = {xr[i].x, xr[i].y, xr[i].z, xr[i].w};
        __half hh[4], hl[4];
        #pragma unroll
        for (int j = 0; j < 4; ++j) {
            hh[j] = __float2half_rn(f[j]);
            hl[j] = __float2half_rn(f[j] - __half2float(hh[j]));
        }
        *(uint2*)(smem + sw)         = make_uint2(pack_h2(hh[0], hh[1]), pack_h2(hh[2], hh[3]));
        *(uint2*)(smem + PLANE + sw) = make_uint2(pack_h2(hl[0], hl[1]), pack_h2(hl[2], hl[3]));
    }
    // x chunk1 -> regs
    #pragma unroll
    for (int i = 0; i < 4; ++i) xr[i] = *(const float4*)(xbase + KC + 4 * i);
    // B chunk0, chunk1 via cp.async (two groups)
    #pragma unroll
    for (int j = 0; j < 4; ++j) {
        const int u = tid + 256 * j;             // 0..1023
        const int s = u >> 9, rem = u & 511;
        const int n = rem >> 2, cu = (rem & 3) * 16;
        cp16(sb + OFF_B + (uint32_t)s * PLANE + swz32(n, cu), &g_w[s][n * DK + (cu >> 1)]);
    }
    asm volatile("cp.async.commit_group;" ::: "memory");
    #pragma unroll
    for (int j = 0; j < 4; ++j) {
        const int u = tid + 256 * j;
        const int s = u >> 9, rem = u & 511;
        const int n = rem >> 2, cu = (rem & 3) * 16;
        cp16(sb + OFF_B + (uint32_t)(2 + s) * PLANE + swz32(n, cu),
             &g_w[s][n * DK + KC + (cu >> 1)]);
    }
    asm volatile("cp.async.commit_group;" ::: "memory");
    // G0 complete for THIS thread, then barrier publishes to all threads.
    asm volatile("cp.async.wait_group 1;" ::: "memory");
    __syncthreads();     // A[0] + B[0] visible block-wide

    #pragma unroll 1
    for (int c = 0; c < NCHUNK; ++c) {
        const int b = c & 1;
        const int k2 = ((c + 2) & (NCHUNK - 1)) * KC;   // x for chunk c+2 (wraps, safe)
        const bool cvt = (c + 1 < NCHUNK);
        char* An = smem + (uint32_t)((1 - b) * 2) * PLANE;  // convert dest (chunk c+1)

        const uint32_t Ah = sb + (uint32_t)(b * 2) * PLANE;
        const uint32_t Al = Ah + PLANE;
        const uint32_t Bh = sb + OFF_B + (uint32_t)(b * 2) * PLANE;
        const uint32_t Bl = Bh + PLANE;

        #pragma unroll
        for (int ks = 0; ks < 2; ++ks) {
            const uint32_t kb = (uint32_t)(ks * 32);
            const uint32_t ca = (kb + cbA) ^ xorA;
            const uint32_t cc = (kb + cbB) ^ xorB;
            uint32_t a[4][4], bh[8], bl[8];
            #pragma unroll
            for (int mt = 0; mt < 4; ++mt)
                ldsm4(a[mt][0], a[mt][1], a[mt][2], a[mt][3], Ah + rowA + mt * 1024 + ca);
            ldsm4(bh[0], bh[1], bh[2], bh[3], Bh + rowB + cc);
            ldsm4(bh[4], bh[5], bh[6], bh[7], Bh + rowB + 1024 + cc);
            ldsm4(bl[0], bl[1], bl[2], bl[3], Bl + rowB + cc);
            ldsm4(bl[4], bl[5], bl[6], bl[7], Bl + rowB + 1024 + cc);

            // product hh
            #pragma unroll
            for (int mt = 0; mt < 4; ++mt)
                #pragma unroll
                for (int nt = 0; nt < 4; ++nt)
                    mma16816(acc[mt][nt], a[mt], bh[2 * nt], bh[2 * nt + 1]);

            // interleaved convert of xr block 2*ks -> A[1-b]
            if (cvt) {
                const int i = 2 * ks;
                const uint32_t sw = rowX + (((uint32_t)((h_x + 4 * i) * 2)) ^ xorX);
                float f[4] = {xr[i].x, xr[i].y, xr[i].z, xr[i].w};
                __half hh4[4], hl4[4];
                #pragma unroll
                for (int j = 0; j < 4; ++j) {
                    hh4[j] = __float2half_rn(f[j]);
                    hl4[j] = __float2half_rn(f[j] - __half2float(hh4[j]));
                }
                *(uint2*)(An + sw)         = make_uint2(pack_h2(hh4[0], hh4[1]), pack_h2(hh4[2], hh4[3]));
                *(uint2*)(An + PLANE + sw) = make_uint2(pack_h2(hl4[0], hl4[1]), pack_h2(hl4[2], hl4[3]));
            }

            // product hl
            #pragma unroll
            for (int mt = 0; mt < 4; ++mt)
                #pragma unroll
                for (int nt = 0; nt < 4; ++nt)
                    mma16816(acc[mt][nt], a[mt], bl[2 * nt], bl[2 * nt + 1]);

            #pragma unroll
            for (int mt = 0; mt < 4; ++mt)
                ldsm4(a[mt][0], a[mt][1], a[mt][2], a[mt][3], Al + rowA + mt * 1024 + ca);

            // interleaved convert of xr block 2*ks+1, then prefetch x(c+2)
            if (cvt) {
                const int i = 2 * ks + 1;
                const uint32_t sw = rowX + (((uint32_t)((h_x + 4 * i) * 2)) ^ xorX);
                float f[4] = {xr[i].x, xr[i].y, xr[i].z, xr[i].w};
                __half hh4[4], hl4[4];
                #pragma unroll
                for (int j = 0; j < 4; ++j) {
                    hh4[j] = __float2half_rn(f[j]);
                    hl4[j] = __float2half_rn(f[j] - __half2float(hh4[j]));
                }
                *(uint2*)(An + sw)         = make_uint2(pack_h2(hh4[0], hh4[1]), pack_h2(hh4[2], hh4[3]));
                *(uint2*)(An + PLANE + sw) = make_uint2(pack_h2(hl4[0], hl4[1]), pack_h2(hl4[2], hl4[3]));
            }
            xr[2 * ks]     = *(const float4*)(xbase + k2 + 4 * (2 * ks));
            xr[2 * ks + 1] = *(const float4*)(xbase + k2 + 4 * (2 * ks + 1));

            // product lh
            #pragma unroll
            for (int mt = 0; mt < 4; ++mt)
                #pragma unroll
                for (int nt = 0; nt < 4; ++nt)
                    mma16816(acc[mt][nt], a[mt], bh[2 * nt], bh[2 * nt + 1]);
        }

        // prefetch B chunk c+2 into buffer b (reads of B[b] done above by this
        // thread; other threads' reads are covered because they also finish
        // before their own commit+barrier below). Commit ALWAYS (empty on
        // tail) so group accounting stays exact.
        if (c + 2 < NCHUNK) {
            const int kB = (c + 2) * KC;
            #pragma unroll
            for (int j = 0; j < 4; ++j) {
                const int u = tid + 256 * j;
                const int s = u >> 9, rem = u & 511;
                const int n = rem >> 2, cu = (rem & 3) * 16;
                cp16(sb + OFF_B + (uint32_t)(b * 2 + s) * PLANE + swz32(n, cu),
                     &g_w[s][n * DK + kB + (cu >> 1)]);
            }
        }
        asm volatile("cp.async.commit_group;" ::: "memory");
        // Ensure THIS thread's G(c+1) is complete, then publish everything
        // (B[c+1] data + A[1-b] converts) to the whole block.
        asm volatile("cp.async.wait_group 1;" ::: "memory");
        __syncthreads();
    }

    // ---- stage C (scaled 1/32) + eps to smem, fused top-2 epilogue ----
    float* Cs = (float*)smem;                    // [128][130]
    float* Es = (float*)(smem + 66560);          // [128][66]
    {
        const float INV32 = 0.03125f;
        const int crow = wm * 64 + (lane >> 2);
        const int ccol = wq * 32 + (lane & 3) * 2;
        #pragma unroll
        for (int mt = 0; mt < 4; ++mt)
            #pragma unroll
            for (int nt = 0; nt < 4; ++nt) {
                float* p0 = Cs + (crow + mt * 16) * 130 + ccol + nt * 8;
                p0[0] = acc[mt][nt][0] * INV32; p0[1] = acc[mt][nt][1] * INV32;
                float* p1 = p0 + 8 * 130;
                p1[0] = acc[mt][nt][2] * INV32; p1[1] = acc[mt][nt][3] * INV32;
            }
        const float4* eg = (const float4*)(eps + (size_t)row0 * NE);
        #pragma unroll
        for (int i4 = 0; i4 < 8; ++i4) {
            int u = tid + 256 * i4;                 // 0..2047
            float4 v = eg[u];
            int r = u >> 4, e = (u & 15) * 4;
            float* d = Es + r * 66 + e;
            d[0] = v.x; d[1] = v.y; d[2] = v.z; d[3] = v.w;
        }
    }
    __syncthreads();

    if (tid < BM) {
        const int r = tid;
        const size_t n = (size_t)row0 + r;
        const float* lg = Cs + r * 130;
        const float* er = Es + r * 66;
        const float NEG = __int_as_float(0xff800000);
        float m1 = NEG, m2 = NEG; int i1 = 0, i2 = 0;
        #pragma unroll
        for (int e = 0; e < NE; ++e) {
            float v = lg[e] + er[e] * softplusf(lg[e + 64]);
            if (v > m1) { m2 = m1; i2 = i1; m1 = v; i1 = e; }
            else if (v > m2) { m2 = v; i2 = e; }
        }
        float ee = expf(m2 - m1);
        float inv = 1.0f / (1.0f + ee);
        out[n * NE + i1] = inv;
        out[n * NE + i2] = ee * inv;
        if (write_idx) {
            idx_out[n * 2 + 0] = (float)i1;
            idx_out[n * 2 + 1] = (float)i2;
        }
    }
}

extern "C" void kernel_launch(void* const* d_in, const int* in_sizes, int n_in,
                              void* d_out, int out_size)
{
    const float* x   = (const float*)d_in[0];
    const float* wr  = (const float*)d_in[1];
    const float* wn  = (const float*)d_in[2];
    const float* eps = (const float*)d_in[3];
    float* out = (float*)d_out;

    const int N = in_sizes[3] / NE;
    const int write_idx = (out_size >= N * NE + N * 2) ? 1 : 0;
    float* idx_out = out + (size_t)N * NE;

    prep_weights<<<(128 * DK) / 256, 256>>>(wr, wn);

    cudaFuncSetAttribute(router_gemm,
                         cudaFuncAttributeMaxDynamicSharedMemorySize, SMEM_BYTES);
    router_gemm<<<N / BM, 256, SMEM_BYTES>>>(x, eps, out, idx_out, write_idx);
}

// round 9
// speedup vs baseline: 1.2999x; 1.2999x over previous
#include <cuda_runtime.h>
#include <cuda_fp16.h>
#include <cstdint>

// TopKNoisyRouter: fused dual GEMM [N,1024]x[1024,128], fp16 2-way split
// (3 HMMA products, fp32 accum, W pre-scaled by 32). Round-5 structure
// (phase-separated convert -> wait+sync -> MMA; one barrier/chunk) with B
// triple-buffered so cp.async runs at prefetch distance 2 and the
// top-of-chunk wait is wait_group 1 on a two-chunk-old copy (never blocks).
// Per-thread wait BEFORE __syncthreads keeps cp.async visibility race-free.
// 2 CTAs/SM. Fused noisy-top-2 + softmax epilogue.

#define DK 1024
#define NE 64
#define BM 128
#define KC 32
#define NCHUNK (DK / KC)      // 32
#define PLANE 8192            // 128 rows x 32 fp16 (64B rows)
#define OFF_B (4 * PLANE)     // A: 2 bufs x 2 planes; B: 3 bufs x 2 planes
#define SMEM_BYTES 100352     // max(gemm 80KB, epilogue C+eps staging 100KB)

__device__ __half g_w[2][128 * DK];   // fp16(32w), fp16(32w - hi); K-major

__device__ __forceinline__ uint32_t smem_u32(const void* p) {
    uint32_t a;
    asm("{ .reg .u64 t; cvta.to.shared.u64 t, %1; cvt.u32.u64 %0, t; }" : "=r"(a) : "l"(p));
    return a;
}
__device__ __forceinline__ uint32_t swz32(uint32_t r, uint32_t c) {
    return (r >> 1) * 128 + (r & 1) * 64 + (c ^ (((r >> 1) & 3) << 4));
}
__device__ __forceinline__ void cp16(uint32_t dst, const void* src) {
    asm volatile("cp.async.cg.shared.global [%0], [%1], 16;" :: "r"(dst), "l"(src));
}
__device__ __forceinline__ void ldsm4(uint32_t& r0, uint32_t& r1, uint32_t& r2,
                                      uint32_t& r3, uint32_t addr) {
    asm volatile("ldmatrix.sync.aligned.m8n8.x4.shared.b16 {%0,%1,%2,%3}, [%4];"
                 : "=r"(r0), "=r"(r1), "=r"(r2), "=r"(r3) : "r"(addr));
}
__device__ __forceinline__ void mma16816(float* c, const uint32_t* a,
                                         uint32_t b0, uint32_t b1) {
    asm volatile("mma.sync.aligned.m16n8k16.row.col.f32.f16.f16.f32 "
                 "{%0,%1,%2,%3}, {%4,%5,%6,%7}, {%8,%9}, {%0,%1,%2,%3};"
                 : "+f"(c[0]), "+f"(c[1]), "+f"(c[2]), "+f"(c[3])
                 : "r"(a[0]), "r"(a[1]), "r"(a[2]), "r"(a[3]), "r"(b0), "r"(b1));
}
__device__ __forceinline__ float softplusf(float v) {
    return fmaxf(v, 0.0f) + log1pf(expf(-fabsf(v)));
}
__device__ __forceinline__ uint32_t pack_h2(__half lo, __half hi) {
    return (uint32_t)__half_as_ushort(lo) | ((uint32_t)__half_as_ushort(hi) << 16);
}

__global__ void prep_weights(const float* __restrict__ wr, const float* __restrict__ wn) {
    int i = blockIdx.x * blockDim.x + threadIdx.x;    // 0 .. 128*1024-1
    int e = i >> 10, k = i & 1023;
    float v = 32.0f * ((e < NE) ? wr[e * DK + k] : wn[(e - NE) * DK + k]);
    __half h = __float2half_rn(v);
    g_w[0][i] = h;
    g_w[1][i] = __float2half_rn(v - __half2float(h));
}

__global__ __launch_bounds__(256, 2)
void router_gemm(const float* __restrict__ x, const float* __restrict__ eps,
                 float* __restrict__ out, float* __restrict__ idx_out, int write_idx)
{
    extern __shared__ char smem[];
    const uint32_t sb = smem_u32(smem);
    const int tid = threadIdx.x;
    const int lane = tid & 31, wid = tid >> 5;
    const int wm = wid & 1, wq = wid >> 1;        // warp tile 64x32 at (wm*64, wq*32)
    const int row0 = blockIdx.x * BM;

    // coalesced zero-fill of this block's output tile [128 x 64]
    {
        float4 z = make_float4(0.f, 0.f, 0.f, 0.f);
        float4* ot = (float4*)(out + (size_t)row0 * NE);
        #pragma unroll
        for (int i = 0; i < 8; ++i) ot[tid + 256 * i] = z;
    }

    // ldmatrix per-lane address pieces
    const int rA = wm * 64 + (lane & 15);
    const uint32_t rowA = (uint32_t)((rA >> 1) * 128 + (rA & 1) * 64);
    const uint32_t xorA = (uint32_t)(((rA >> 1) & 3) << 4);
    const uint32_t cbA  = (uint32_t)((lane >> 4) * 16);
    const int rB = wq * 32 + (lane & 7) + ((lane >> 4) << 3);
    const uint32_t rowB = (uint32_t)((rB >> 1) * 128 + (rB & 1) * 64);
    const uint32_t xorB = (uint32_t)(((rB >> 1) & 3) << 4);
    const uint32_t cbB  = (uint32_t)(((lane >> 3) & 1) * 16);

    // x staging: thread covers row r_x, 16 floats at float-offset h_x
    const int r_x = tid >> 1;
    const int h_x = (tid & 1) * 16;
    const float* xbase = x + (size_t)(row0 + r_x) * DK + h_x;
    const uint32_t rowX = (uint32_t)((r_x >> 1) * 128 + (r_x & 1) * 64);
    const uint32_t xorX = (uint32_t)(((r_x >> 1) & 3) << 4);

    float acc[4][4][4];
    #pragma unroll
    for (int mt = 0; mt < 4; ++mt)
        #pragma unroll
        for (int nt = 0; nt < 4; ++nt)
            #pragma unroll
            for (int q = 0; q < 4; ++q) acc[mt][nt][q] = 0.f;

    // ---- prologue: x chunk0 -> regs; B chunks 0,1 -> cp.async (2 groups) ----
    float4 xr[4];
    #pragma unroll
    for (int i = 0; i < 4; ++i) xr[i] = *(const float4*)(xbase + 4 * i);
    #pragma unroll
    for (int j = 0; j < 4; ++j) {
        const int u = tid + 256 * j;             // 0..1023
        const int s = u >> 9, rem = u & 511;
        const int n = rem >> 2, cu = (rem & 3) * 16;
        cp16(sb + OFF_B + (uint32_t)s * PLANE + swz32(n, cu), &g_w[s][n * DK + (cu >> 1)]);
    }
    asm volatile("cp.async.commit_group;" ::: "memory");
    #pragma unroll
    for (int j = 0; j < 4; ++j) {
        const int u = tid + 256 * j;
        const int s = u >> 9, rem = u & 511;
        const int n = rem >> 2, cu = (rem & 3) * 16;
        cp16(sb + OFF_B + (uint32_t)(2 + s) * PLANE + swz32(n, cu),
             &g_w[s][n * DK + KC + (cu >> 1)]);
    }
    asm volatile("cp.async.commit_group;" ::: "memory");

    int br = 0;   // B read buffer  (c % 3)
    int bp = 2;   // B prefetch buffer ((c+2) % 3)

    #pragma unroll 1
    for (int c = 0; c < NCHUNK; ++c) {
        const int b = c & 1;
        const int kn = ((c + 1) & (NCHUNK - 1)) * KC;   // next x chunk (wraps, safe)
        char* Ab = smem + (uint32_t)(b * 2) * PLANE;

        // ---- convert x regs (chunk c) -> A[b]; prefetch next x into regs ----
        #pragma unroll
        for (int i = 0; i < 4; ++i) {
            float4 f4 = xr[i];
            xr[i] = *(const float4*)(xbase + kn + 4 * i);
            const uint32_t sw = rowX + (((uint32_t)((h_x + 4 * i) * 2)) ^ xorX);
            float f[4] = {f4.x, f4.y, f4.z, f4.w};
            __half hh[4], hl[4];
            #pragma unroll
            for (int j = 0; j < 4; ++j) {
                hh[j] = __float2half_rn(f[j]);
                hl[j] = __float2half_rn(f[j] - __half2float(hh[j]));
            }
            *(uint2*)(Ab + sw)         = make_uint2(pack_h2(hh[0], hh[1]), pack_h2(hh[2], hh[3]));
            *(uint2*)(Ab + PLANE + sw) = make_uint2(pack_h2(hl[0], hl[1]), pack_h2(hl[2], hl[3]));
        }

        // B group for chunk c complete for THIS thread (wait allows only the
        // most recent group — chunk c+1 — to stay pending), then publish.
        asm volatile("cp.async.wait_group 1;" ::: "memory");
        __syncthreads();                        // A[b] + B[br] visible

        // ---- prefetch B chunk c+2 into buffer bp (its old contents were
        // consumed in chunk c-1, fully before the barrier above). Commit
        // ALWAYS (empty on tail) to keep group accounting exact. ----
        if (c + 2 < NCHUNK) {
            const int kB = (c + 2) * KC;
            #pragma unroll
            for (int j = 0; j < 4; ++j) {
                const int u = tid + 256 * j;
                const int s = u >> 9, rem = u & 511;
                const int n = rem >> 2, cu = (rem & 3) * 16;
                cp16(sb + OFF_B + (uint32_t)(bp * 2 + s) * PLANE + swz32(n, cu),
                     &g_w[s][n * DK + kB + (cu >> 1)]);
            }
        }
        asm volatile("cp.async.commit_group;" ::: "memory");

        // ---- MMA: 3 split products over 2 k16 steps ----
        const uint32_t Ah = sb + (uint32_t)(b * 2) * PLANE;
        const uint32_t Al = Ah + PLANE;
        const uint32_t Bh = sb + OFF_B + (uint32_t)(br * 2) * PLANE;
        const uint32_t Bl = Bh + PLANE;
        #pragma unroll
        for (int ks = 0; ks < 2; ++ks) {
            const uint32_t kb = (uint32_t)(ks * 32);
            const uint32_t ca = (kb + cbA) ^ xorA;
            const uint32_t cc = (kb + cbB) ^ xorB;
            uint32_t a[4][4], bh[8], bl[8];
            #pragma unroll
            for (int mt = 0; mt < 4; ++mt)
                ldsm4(a[mt][0], a[mt][1], a[mt][2], a[mt][3], Ah + rowA + mt * 1024 + ca);
            ldsm4(bh[0], bh[1], bh[2], bh[3], Bh + rowB + cc);
            ldsm4(bh[4], bh[5], bh[6], bh[7], Bh + rowB + 1024 + cc);
            ldsm4(bl[0], bl[1], bl[2], bl[3], Bl + rowB + cc);
            ldsm4(bl[4], bl[5], bl[6], bl[7], Bl + rowB + 1024 + cc);
            #pragma unroll
            for (int mt = 0; mt < 4; ++mt)
                #pragma unroll
                for (int nt = 0; nt < 4; ++nt)
                    mma16816(acc[mt][nt], a[mt], bh[2 * nt], bh[2 * nt + 1]);
            #pragma unroll
            for (int mt = 0; mt < 4; ++mt)
                #pragma unroll
                for (int nt = 0; nt < 4; ++nt)
                    mma16816(acc[mt][nt], a[mt], bl[2 * nt], bl[2 * nt + 1]);
            #pragma unroll
            for (int mt = 0; mt < 4; ++mt)
                ldsm4(a[mt][0], a[mt][1], a[mt][2], a[mt][3], Al + rowA + mt * 1024 + ca);
            #pragma unroll
            for (int mt = 0; mt < 4; ++mt)
                #pragma unroll
                for (int nt = 0; nt < 4; ++nt)
                    mma16816(acc[mt][nt], a[mt], bh[2 * nt], bh[2 * nt + 1]);
        }

        br = (br == 2) ? 0 : br + 1;
        bp = (bp == 2) ? 0 : bp + 1;
    }
    __syncthreads();

    // ---- stage C (scaled 1/32) + eps to smem, fused top-2 epilogue ----
    float* Cs = (float*)smem;                    // [128][130]
    float* Es = (float*)(smem + 66560);          // [128][66]
    {
        const float INV32 = 0.03125f;
        const int crow = wm * 64 + (lane >> 2);
        const int ccol = wq * 32 + (lane & 3) * 2;
        #pragma unroll
        for (int mt = 0; mt < 4; ++mt)
            #pragma unroll
            for (int nt = 0; nt < 4; ++nt) {
                float* p0 = Cs + (crow + mt * 16) * 130 + ccol + nt * 8;
                p0[0] = acc[mt][nt][0] * INV32; p0[1] = acc[mt][nt][1] * INV32;
                float* p1 = p0 + 8 * 130;
                p1[0] = acc[mt][nt][2] * INV32; p1[1] = acc[mt][nt][3] * INV32;
            }
        const float4* eg = (const float4*)(eps + (size_t)row0 * NE);
        #pragma unroll
        for (int i4 = 0; i4 < 8; ++i4) {
            int u = tid + 256 * i4;                 // 0..2047
            float4 v = eg[u];
            int r = u >> 4, e = (u & 15) * 4;
            float* d = Es + r * 66 + e;
            d[0] = v.x; d[1] = v.y; d[2] = v.z; d[3] = v.w;
        }
    }
    __syncthreads();

    if (tid < BM) {
        const int r = tid;
        const size_t n = (size_t)row0 + r;
        const float* lg = Cs + r * 130;
        const float* er = Es + r * 66;
        const float NEG = __int_as_float(0xff800000);
        float m1 = NEG, m2 = NEG; int i1 = 0, i2 = 0;
        #pragma unroll
        for (int e = 0; e < NE; ++e) {
            float v = lg[e] + er[e] * softplusf(lg[e + 64]);
            if (v > m1) { m2 = m1; i2 = i1; m1 = v; i1 = e; }
            else if (v > m2) { m2 = v; i2 = e; }
        }
        float ee = expf(m2 - m1);
        float inv = 1.0f / (1.0f + ee);
        out[n * NE + i1] = inv;
        out[n * NE + i2] = ee * inv;
        if (write_idx) {
            idx_out[n * 2 + 0] = (float)i1;
            idx_out[n * 2 + 1] = (float)i2;
        }
    }
}

extern "C" void kernel_launch(void* const* d_in, const int* in_sizes, int n_in,
                              void* d_out, int out_size)
{
    const float* x   = (const float*)d_in[0];
    const float* wr  = (const float*)d_in[1];
    const float* wn  = (const float*)d_in[2];
    const float* eps = (const float*)d_in[3];
    float* out = (float*)d_out;

    const int N = in_sizes[3] / NE;
    const int write_idx = (out_size >= N * NE + N * 2) ? 1 : 0;
    float* idx_out = out + (size_t)N * NE;

    prep_weights<<<(128 * DK) / 256, 256>>>(wr, wn);

    cudaFuncSetAttribute(router_gemm,
                         cudaFuncAttributeMaxDynamicSharedMemorySize, SMEM_BYTES);
    router_gemm<<<N / BM, 256, SMEM_BYTES>>>(x, eps, out, idx_out, write_idx);
}